// round 8
// baseline (speedup 1.0000x reference)
#include <cuda_runtime.h>
#include <math.h>

static constexpr int BATCH = 64;
static constexpr int H  = 256;
static constexpr int W  = 256;
static constexpr int HW = H * W;          // 65536
static constexpr int HW4 = HW / 4;        // 16384 float4 groups per channel
static constexpr int NK = 68;
static constexpr int NPROD = BATCH;                 // 64 producer blocks
static constexpr int NCONS = (BATCH * HW4) / 256;   // 4096 consumer blocks
static constexpr int NBLK  = NPROD + NCONS;         // 4160 total

// Params padded to one 128B cache line per batch (32 floats): slots 0..11 used.
__device__ float        g_params[BATCH * 32];
// Flags padded to one 128B line per batch (32 ints): slot 0 used.
__device__ int          g_flag[BATCH * 32];
__device__ unsigned int g_done;

__device__ __forceinline__ float warp_sum(float v) {
    #pragma unroll
    for (int o = 16; o > 0; o >>= 1) v += __shfl_down_sync(0xffffffffu, v, o);
    return v;
}

__device__ __forceinline__ int ld_acquire_gpu(const int* p) {
    int v;
    asm volatile("ld.acquire.gpu.s32 %0, [%1];" : "=r"(v) : "l"(p) : "memory");
    return v;
}

__device__ __forceinline__ void st_release_gpu(int* p, int v) {
    asm volatile("st.release.gpu.s32 [%0], %1;" :: "l"(p), "r"(v) : "memory");
}

// ---------------------------------------------------------------------------
// Single fused kernel.
//   blocks [0,64):    estimate batch b, publish params + flag (release).
//   blocks [64,4160): issue bulk loads, spin-acquire flag, transform, store.
// Producers are in wave 1 (blockIdx 0..63 scheduled first) -> no deadlock.
// Last-finishing block resets flags + counter so graph replays start clean.
// ---------------------------------------------------------------------------
__global__ void __launch_bounds__(256)
fused_overlap_kernel(const float* __restrict__ Off,
                     const float* __restrict__ Pos,
                     const float* __restrict__ Mp,
                     const int*   __restrict__ uv,
                     float*       __restrict__ Out)
{
    const int bid = blockIdx.x;
    const int tid = threadIdx.x;

    if (bid < NPROD) {
        // ======================= PRODUCER =======================
        const int b    = bid;
        const int wid  = tid >> 5;
        const int lane = tid & 31;

        __shared__ float part[16][8];

        float s0 = 0.f, s1 = 0.f, s2 = 0.f;
        float d0 = 0.f, d1 = 0.f, d2 = 0.f;
        if (tid < NK) {
            const int h = __ldg(&uv[2 * tid + 0]);
            const int w = __ldg(&uv[2 * tid + 1]);
            const int base = b * 3 * HW + h * W + w;
            const int mb   = h * W + w;
            // offsetmap = (Offset*4 + mean) * REVERT, REVERT = [1,-1,1]
            s0 =  fmaf(Off[base         ], 4.0f, Mp[mb         ]);
            s1 = -fmaf(Off[base +    HW ], 4.0f, Mp[mb +    HW ]);
            s2 =  fmaf(Off[base + 2*HW  ], 4.0f, Mp[mb + 2*HW  ]);
            d0 = Pos[base];
            d1 = Pos[base + HW];
            d2 = Pos[base + 2 * HW];
        }

        float m[16];
        m[0]  = s0;       m[1]  = s1;       m[2]  = s2;
        m[3]  = d0;       m[4]  = d1;       m[5]  = d2;
        m[6]  = d0 * s0;  m[7]  = d0 * s1;  m[8]  = d0 * s2;
        m[9]  = d1 * s0;  m[10] = d1 * s1;  m[11] = d1 * s2;
        m[12] = d2 * s0;  m[13] = d2 * s1;  m[14] = d2 * s2;
        m[15] = s0 * s0 + s1 * s1 + s2 * s2;

        #pragma unroll
        for (int k = 0; k < 16; k++) {
            const float v = warp_sum(m[k]);
            if (lane == 0) part[k][wid] = v;
        }
        __syncthreads();

        if (tid == 0) {
            const float inv_n = 1.0f / NK;
            float S[16];
            #pragma unroll
            for (int k = 0; k < 16; k++) {
                float t = 0.f;
                #pragma unroll
                for (int j = 0; j < 8; j++) t += part[k][j];
                S[k] = t * inv_n;
            }

            const float mus0 = S[0], mus1 = S[1], mus2 = S[2];
            const float mud0 = S[3], mud1 = S[4], mud2 = S[5];

            float A[3][3];
            A[0][0] = S[6]  - mud0*mus0; A[0][1] = S[7]  - mud0*mus1; A[0][2] = S[8]  - mud0*mus2;
            A[1][0] = S[9]  - mud1*mus0; A[1][1] = S[10] - mud1*mus1; A[1][2] = S[11] - mud1*mus2;
            A[2][0] = S[12] - mud2*mus0; A[2][1] = S[13] - mud2*mus1; A[2][2] = S[14] - mud2*mus2;
            const float var_s = S[15] - (mus0*mus0 + mus1*mus1 + mus2*mus2);

            const float detA =
                  A[0][0] * (A[1][1]*A[2][2] - A[1][2]*A[2][1])
                - A[0][1] * (A[1][0]*A[2][2] - A[1][2]*A[2][0])
                + A[0][2] * (A[1][0]*A[2][1] - A[1][1]*A[2][0]);

            float Bm[3][3], Vm[3][3] = {{1,0,0},{0,1,0},{0,0,1}};
            #pragma unroll
            for (int i = 0; i < 3; i++)
                #pragma unroll
                for (int j = 0; j < 3; j++) {
                    float acc = 0.0f;
                    #pragma unroll
                    for (int k = 0; k < 3; k++) acc += A[k][i] * A[k][j];
                    Bm[i][j] = acc;
                }

            const int PP[3] = {0, 0, 1}, QQ[3] = {1, 2, 2};
            #pragma unroll 1
            for (int sweep = 0; sweep < 5; sweep++) {
                #pragma unroll
                for (int r = 0; r < 3; r++) {
                    const int p = PP[r], q = QQ[r];
                    const float apq = Bm[p][q];
                    if (fabsf(apq) < 1e-30f) continue;
                    const float theta = (Bm[q][q] - Bm[p][p]) / (2.0f * apq);
                    const float tt = ((theta >= 0.0f) ? 1.0f : -1.0f) /
                                     (fabsf(theta) + sqrtf(theta * theta + 1.0f));
                    const float c = rsqrtf(tt * tt + 1.0f);
                    const float s = tt * c;
                    #pragma unroll
                    for (int k = 0; k < 3; k++) {
                        const float bkp = Bm[k][p], bkq = Bm[k][q];
                        Bm[k][p] = c * bkp - s * bkq;
                        Bm[k][q] = s * bkp + c * bkq;
                    }
                    #pragma unroll
                    for (int k = 0; k < 3; k++) {
                        const float bpk = Bm[p][k], bqk = Bm[q][k];
                        Bm[p][k] = c * bpk - s * bqk;
                        Bm[q][k] = s * bpk + c * bqk;
                    }
                    #pragma unroll
                    for (int k = 0; k < 3; k++) {
                        const float vkp = Vm[k][p], vkq = Vm[k][q];
                        Vm[k][p] = c * vkp - s * vkq;
                        Vm[k][q] = s * vkp + c * vkq;
                    }
                }
            }

            float wv[3] = {Bm[0][0], Bm[1][1], Bm[2][2]};
            int id[3] = {0, 1, 2};
            if (wv[id[0]] < wv[id[1]]) { int t = id[0]; id[0] = id[1]; id[1] = t; }
            if (wv[id[1]] < wv[id[2]]) { int t = id[1]; id[1] = id[2]; id[2] = t; }
            if (wv[id[0]] < wv[id[1]]) { int t = id[0]; id[0] = id[1]; id[1] = t; }

            float U[3][3], Vc[3][3], sv[3];
            #pragma unroll
            for (int i = 0; i < 3; i++) {
                const int j = id[i];
                const float v0 = Vm[0][j], v1 = Vm[1][j], v2 = Vm[2][j];
                const float u0 = A[0][0]*v0 + A[0][1]*v1 + A[0][2]*v2;
                const float u1 = A[1][0]*v0 + A[1][1]*v1 + A[1][2]*v2;
                const float u2 = A[2][0]*v0 + A[2][1]*v1 + A[2][2]*v2;
                const float nu = sqrtf(u0*u0 + u1*u1 + u2*u2);
                sv[i] = nu;
                const float inv = (nu > 1e-30f) ? 1.0f / nu : 0.0f;
                U[0][i] = u0 * inv; U[1][i] = u1 * inv; U[2][i] = u2 * inv;
                Vc[0][i] = v0; Vc[1][i] = v1; Vc[2][i] = v2;
            }

            const float d3 = (detA < 0.0f) ? -1.0f : 1.0f;
            const float dd[3] = {1.0f, 1.0f, d3};
            const float scale = (sv[0] + sv[1] + d3 * sv[2]) / var_s;

            float* outp = g_params + b * 32;
            #pragma unroll
            for (int r = 0; r < 3; r++) {
                float row[3];
                #pragma unroll
                for (int c = 0; c < 3; c++) {
                    float acc = 0.0f;
                    #pragma unroll
                    for (int i = 0; i < 3; i++) acc += dd[i] * U[r][i] * Vc[c][i];
                    row[c] = scale * acc;
                    outp[r * 3 + c] = row[c];
                }
                outp[9 + r] = ((r == 0) ? mud0 : (r == 1) ? mud1 : mud2)
                    - (row[0] * mus0 + row[1] * mus1 + row[2] * mus2);
            }
            __threadfence();                       // params before flag
            st_release_gpu(&g_flag[b * 32], 1);    // publish
        }
    } else {
        // ======================= CONSUMER =======================
        const int cid = bid - NPROD;
        const int idx = cid * 256 + tid;
        const int b   = idx >> 14;
        const int g   = idx & 16383;
        const int base = b * 3 * HW4 + g;

        const float4* Off4 = (const float4*)Off;
        const float4* Mp4  = (const float4*)Mp;
        float4*       Out4 = (float4*)Out;

        // Start the memory stream immediately (independent of producer).
        const float4 o0 = Off4[base];
        const float4 o1 = Off4[base + HW4];
        const float4 o2 = Off4[base + 2 * HW4];
        const float4 m0 = Mp4[g];
        const float4 m1 = Mp4[g + HW4];
        const float4 m2 = Mp4[g + 2 * HW4];

        // Wait for this batch's params.
        if (tid == 0) {
            while (ld_acquire_gpu(&g_flag[b * 32]) == 0) __nanosleep(64);
        }
        __syncthreads();

        // L1-bypass loads: a co-resident block of another batch must not feed
        // us a stale L1 line (L1 is incoherent within a launch).
        const float* p = g_params + b * 32;
        const float p00 = __ldcg(p + 0), p01 = __ldcg(p + 1), p02 = __ldcg(p + 2);
        const float p10 = __ldcg(p + 3), p11 = __ldcg(p + 4), p12 = __ldcg(p + 5);
        const float p20 = __ldcg(p + 6), p21 = __ldcg(p + 7), p22 = __ldcg(p + 8);
        const float t0  = __ldcg(p + 9), t1  = __ldcg(p + 10), t2 = __ldcg(p + 11);

        float4 r0, r1, r2;
#define APPLY_LANE(j)                                                        \
        {                                                                    \
            const float x =  fmaf(o0.j, 4.0f, m0.j);                         \
            const float y = -fmaf(o1.j, 4.0f, m1.j);                         \
            const float z =  fmaf(o2.j, 4.0f, m2.j);                         \
            r0.j = fmaf(p00, x, fmaf(p01, y, fmaf(p02, z, t0)));             \
            r1.j = fmaf(p10, x, fmaf(p11, y, fmaf(p12, z, t1)));             \
            r2.j = fmaf(p20, x, fmaf(p21, y, fmaf(p22, z, t2)));             \
        }
        APPLY_LANE(x)
        APPLY_LANE(y)
        APPLY_LANE(z)
        APPLY_LANE(w)
#undef APPLY_LANE

        Out4[base]           = r0;
        Out4[base + HW4]     = r1;
        Out4[base + 2 * HW4] = r2;
    }

    // ---- end-of-launch cleanup: last block resets flags + counter ----
    if (tid == 0) {
        const unsigned prev = atomicAdd(&g_done, 1u);
        if (prev == (unsigned)(NBLK - 1)) {
            #pragma unroll
            for (int i = 0; i < BATCH; i++) g_flag[i * 32] = 0;
            __threadfence();
            atomicExch(&g_done, 0u);
        }
    }
}

// ---------------------------------------------------------------------------
extern "C" void kernel_launch(void* const* d_in, const int* in_sizes, int n_in,
                              void* d_out, int out_size)
{
    const float* Off = (const float*)d_in[0];   // [64,3,256,256]
    const float* Pos = (const float*)d_in[1];   // [64,3,256,256]
    const float* Mp  = (const float*)d_in[2];   // [3,256,256]
    const int*   uv  = (const int*)  d_in[3];   // [68,2]
    float*       Out = (float*)d_out;           // [64,3,256,256]

    fused_overlap_kernel<<<NBLK, 256>>>(Off, Pos, Mp, uv, Out);
}

// round 10
// speedup vs baseline: 1.9987x; 1.9987x over previous
#include <cuda_runtime.h>
#include <math.h>

static constexpr int BATCH = 64;
static constexpr int H  = 256;
static constexpr int W  = 256;
static constexpr int HW = H * W;          // 65536
static constexpr int HW4 = HW / 4;        // 16384 float4 groups per channel
static constexpr int NK = 68;

// Per-batch similarity transform: 9 floats sR (row-major [d][c]) + 3 floats t.
__device__ float g_params[BATCH * 12];

// ---------------------------------------------------------------------------
// Kernel 1: per-batch Umeyama estimation (64 blocks x 128 threads).
// smem-transpose reduction (one sync, ILP serial sums) instead of 16 chained
// warp-shuffle reductions; fp32 Jacobi SVD (4 sweeps) on thread 0.
// ---------------------------------------------------------------------------
__global__ void __launch_bounds__(128)
estimate_kernel(const float* __restrict__ Off,
                const float* __restrict__ Pos,
                const float* __restrict__ Mp,
                const int*   __restrict__ uv)
{
    const int b   = blockIdx.x;
    const int tid = threadIdx.x;

    // Padded to 69 columns: 16 reducer threads read stride-69 rows -> the
    // per-iteration bank pattern is 5k mod 32, all distinct (gcd(5,32)=1).
    __shared__ float mom[16][NK + 1];
    __shared__ float ssum[16];

    // ---- gather keypoint pair + write 16 raw moments to smem ----
    if (tid < NK) {
        const int h = __ldg(&uv[2 * tid + 0]);
        const int w = __ldg(&uv[2 * tid + 1]);
        const int base = b * 3 * HW + h * W + w;
        const int mb   = h * W + w;
        // offsetmap = (Offset*4 + mean) * REVERT, REVERT = [1,-1,1]
        const float s0 =  fmaf(Off[base         ], 4.0f, Mp[mb         ]);
        const float s1 = -fmaf(Off[base +    HW ], 4.0f, Mp[mb +    HW ]);
        const float s2 =  fmaf(Off[base + 2*HW  ], 4.0f, Mp[mb + 2*HW  ]);
        const float d0 = Pos[base];
        const float d1 = Pos[base + HW];
        const float d2 = Pos[base + 2 * HW];

        mom[0][tid]  = s0;       mom[1][tid]  = s1;       mom[2][tid]  = s2;
        mom[3][tid]  = d0;       mom[4][tid]  = d1;       mom[5][tid]  = d2;
        mom[6][tid]  = d0 * s0;  mom[7][tid]  = d0 * s1;  mom[8][tid]  = d0 * s2;
        mom[9][tid]  = d1 * s0;  mom[10][tid] = d1 * s1;  mom[11][tid] = d1 * s2;
        mom[12][tid] = d2 * s0;  mom[13][tid] = d2 * s1;  mom[14][tid] = d2 * s2;
        mom[15][tid] = s0 * s0 + s1 * s1 + s2 * s2;
    }
    __syncthreads();

    // ---- 16 threads each sum one moment row (4 accumulators for ILP) ----
    if (tid < 16) {
        float a0 = 0.f, a1 = 0.f, a2 = 0.f, a3 = 0.f;
        #pragma unroll
        for (int i = 0; i < 68; i += 4) {
            a0 += mom[tid][i + 0];
            a1 += mom[tid][i + 1];
            a2 += mom[tid][i + 2];
            a3 += mom[tid][i + 3];
        }
        ssum[tid] = ((a0 + a1) + (a2 + a3)) * (1.0f / NK);
    }
    __syncthreads();

    // ---- thread 0: fp32 3x3 SVD (Jacobi on A^T A, 4 sweeps) + transform ----
    if (tid == 0) {
        const float mus0 = ssum[0], mus1 = ssum[1], mus2 = ssum[2];
        const float mud0 = ssum[3], mud1 = ssum[4], mud2 = ssum[5];

        float A[3][3];
        A[0][0] = ssum[6]  - mud0*mus0; A[0][1] = ssum[7]  - mud0*mus1; A[0][2] = ssum[8]  - mud0*mus2;
        A[1][0] = ssum[9]  - mud1*mus0; A[1][1] = ssum[10] - mud1*mus1; A[1][2] = ssum[11] - mud1*mus2;
        A[2][0] = ssum[12] - mud2*mus0; A[2][1] = ssum[13] - mud2*mus1; A[2][2] = ssum[14] - mud2*mus2;
        const float var_s = ssum[15] - (mus0*mus0 + mus1*mus1 + mus2*mus2);

        const float detA =
              A[0][0] * (A[1][1]*A[2][2] - A[1][2]*A[2][1])
            - A[0][1] * (A[1][0]*A[2][2] - A[1][2]*A[2][0])
            + A[0][2] * (A[1][0]*A[2][1] - A[1][1]*A[2][0]);

        float Bm[3][3], Vm[3][3] = {{1,0,0},{0,1,0},{0,0,1}};
        #pragma unroll
        for (int i = 0; i < 3; i++)
            #pragma unroll
            for (int j = 0; j < 3; j++) {
                float acc = 0.0f;
                #pragma unroll
                for (int k = 0; k < 3; k++) acc += A[k][i] * A[k][j];
                Bm[i][j] = acc;
            }

        const int PP[3] = {0, 0, 1}, QQ[3] = {1, 2, 2};
        #pragma unroll 1
        for (int sweep = 0; sweep < 4; sweep++) {
            #pragma unroll
            for (int r = 0; r < 3; r++) {
                const int p = PP[r], q = QQ[r];
                const float apq = Bm[p][q];
                if (fabsf(apq) < 1e-30f) continue;
                const float theta = (Bm[q][q] - Bm[p][p]) / (2.0f * apq);
                const float tt = ((theta >= 0.0f) ? 1.0f : -1.0f) /
                                 (fabsf(theta) + sqrtf(theta * theta + 1.0f));
                const float c = rsqrtf(tt * tt + 1.0f);
                const float s = tt * c;
                #pragma unroll
                for (int k = 0; k < 3; k++) {
                    const float bkp = Bm[k][p], bkq = Bm[k][q];
                    Bm[k][p] = c * bkp - s * bkq;
                    Bm[k][q] = s * bkp + c * bkq;
                }
                #pragma unroll
                for (int k = 0; k < 3; k++) {
                    const float bpk = Bm[p][k], bqk = Bm[q][k];
                    Bm[p][k] = c * bpk - s * bqk;
                    Bm[q][k] = s * bpk + c * bqk;
                }
                #pragma unroll
                for (int k = 0; k < 3; k++) {
                    const float vkp = Vm[k][p], vkq = Vm[k][q];
                    Vm[k][p] = c * vkp - s * vkq;
                    Vm[k][q] = s * vkp + c * vkq;
                }
            }
        }

        float wv[3] = {Bm[0][0], Bm[1][1], Bm[2][2]};
        int id[3] = {0, 1, 2};
        if (wv[id[0]] < wv[id[1]]) { int t = id[0]; id[0] = id[1]; id[1] = t; }
        if (wv[id[1]] < wv[id[2]]) { int t = id[1]; id[1] = id[2]; id[2] = t; }
        if (wv[id[0]] < wv[id[1]]) { int t = id[0]; id[0] = id[1]; id[1] = t; }

        float U[3][3], Vc[3][3], sv[3];
        #pragma unroll
        for (int i = 0; i < 3; i++) {
            const int j = id[i];
            const float v0 = Vm[0][j], v1 = Vm[1][j], v2 = Vm[2][j];
            const float u0 = A[0][0]*v0 + A[0][1]*v1 + A[0][2]*v2;
            const float u1 = A[1][0]*v0 + A[1][1]*v1 + A[1][2]*v2;
            const float u2 = A[2][0]*v0 + A[2][1]*v1 + A[2][2]*v2;
            const float nu = sqrtf(u0*u0 + u1*u1 + u2*u2);  // sigma_i
            sv[i] = nu;
            const float inv = (nu > 1e-30f) ? 1.0f / nu : 0.0f;
            U[0][i] = u0 * inv; U[1][i] = u1 * inv; U[2][i] = u2 * inv;
            Vc[0][i] = v0; Vc[1][i] = v1; Vc[2][i] = v2;
        }

        const float d3 = (detA < 0.0f) ? -1.0f : 1.0f;
        const float dd[3] = {1.0f, 1.0f, d3};
        const float scale = (sv[0] + sv[1] + d3 * sv[2]) / var_s;

        float* outp = g_params + b * 12;
        #pragma unroll
        for (int r = 0; r < 3; r++) {
            float row[3];
            #pragma unroll
            for (int c = 0; c < 3; c++) {
                float acc = 0.0f;
                #pragma unroll
                for (int i = 0; i < 3; i++) acc += dd[i] * U[r][i] * Vc[c][i];
                row[c] = scale * acc;
                outp[r * 3 + c] = row[c];
            }
            outp[9 + r] = ((r == 0) ? mud0 : (r == 1) ? mud1 : mud2)
                - (row[0] * mus0 + row[1] * mus1 + row[2] * mus2);
        }
    }
}

// ---------------------------------------------------------------------------
// Kernel 2: apply transform (HBM/LTS-bound, float4). Identical to the 15.3us
// version — no cache hints, no PDL; it sits at the LTS throughput ceiling.
// ---------------------------------------------------------------------------
__global__ void __launch_bounds__(256)
apply_kernel(const float4* __restrict__ Off,
             const float4* __restrict__ Mp,
             float4*       __restrict__ Out)
{
    const int idx = blockIdx.x * blockDim.x + threadIdx.x;  // 64*16384 threads
    const int b = idx >> 14;            // 16384 float4 groups per batch image
    const int g = idx & 16383;

    const float* p = g_params + b * 12; // uniform per block -> broadcast loads
    const float p00 = p[0], p01 = p[1], p02 = p[2];
    const float p10 = p[3], p11 = p[4], p12 = p[5];
    const float p20 = p[6], p21 = p[7], p22 = p[8];
    const float t0  = p[9], t1  = p[10], t2 = p[11];

    const int base = b * 3 * HW4 + g;
    const float4 o0 = Off[base];
    const float4 o1 = Off[base + HW4];
    const float4 o2 = Off[base + 2 * HW4];
    const float4 m0 = Mp[g];
    const float4 m1 = Mp[g + HW4];
    const float4 m2 = Mp[g + 2 * HW4];

    float4 r0, r1, r2;

#define APPLY_LANE(j)                                                        \
    {                                                                        \
        const float x =  fmaf(o0.j, 4.0f, m0.j);                             \
        const float y = -fmaf(o1.j, 4.0f, m1.j);                             \
        const float z =  fmaf(o2.j, 4.0f, m2.j);                             \
        r0.j = fmaf(p00, x, fmaf(p01, y, fmaf(p02, z, t0)));                 \
        r1.j = fmaf(p10, x, fmaf(p11, y, fmaf(p12, z, t1)));                 \
        r2.j = fmaf(p20, x, fmaf(p21, y, fmaf(p22, z, t2)));                 \
    }

    APPLY_LANE(x)
    APPLY_LANE(y)
    APPLY_LANE(z)
    APPLY_LANE(w)
#undef APPLY_LANE

    Out[base]           = r0;
    Out[base + HW4]     = r1;
    Out[base + 2 * HW4] = r2;
}

// ---------------------------------------------------------------------------
extern "C" void kernel_launch(void* const* d_in, const int* in_sizes, int n_in,
                              void* d_out, int out_size)
{
    const float* Off = (const float*)d_in[0];   // [64,3,256,256]
    const float* Pos = (const float*)d_in[1];   // [64,3,256,256]
    const float* Mp  = (const float*)d_in[2];   // [3,256,256]
    const int*   uv  = (const int*)  d_in[3];   // [68,2]
    float*       Out = (float*)d_out;           // [64,3,256,256]

    estimate_kernel<<<BATCH, 128>>>(Off, Pos, Mp, uv);

    const int total4 = BATCH * HW4;             // 1,048,576 threads
    apply_kernel<<<total4 / 256, 256>>>((const float4*)Off,
                                        (const float4*)Mp,
                                        (float4*)Out);
}